// round 7
// baseline (speedup 1.0000x reference)
#include <cuda_runtime.h>
#include <cuda_fp16.h>
#include <cstdint>

// Problem constants (fixed for MoEDense_10411000726246)
#define TB 8192     // batch
#define DD 128      // input dim (K)
#define FF 128      // output dim (N)
#define TT 64       // num experts
#define TM 32       // rows per GEMM tile
#define NCTA 148    // persistent CTAs (== #SMs, all co-resident)
#define NSORT 128   // sort CTAs (64 rows each)
#define MAXT 3      // max tiles per CTA (ntiles <= 320 <= 3*148)

// Scratch (no allocations allowed)
__device__ int g_partial[NSORT * TT];
__device__ int g_bar1 = 0, g_bar2 = 0, g_dep = 0;
__device__ int g_rowOrder[TB + TT * TM];          // padded positions
__device__ __half g_Xs[(TB + 1) * 256];           // [row][hi128|lo128], +zero row
__device__ __half g_Wh[TT * DD * FF];             // fp16(W)

// smem buffers (dynamic): two tile buffers
#define ABYTES (TM * 528)                  // 16896 (A row = 256 fp16 + 16B pad)
#define BBYTES (DD * 272)                  // 34816 (B row = 128 fp16 + 16B pad)
#define BUFB   (ABYTES + BBYTES + 512)     // 52224 (+bias)
#define SMTOT  (2 * BUFB)                  // 104448

// ---------------------------------------------------------------------------
__device__ __forceinline__ uint32_t smem_u32(const void* p) {
    uint32_t a;
    asm("{ .reg .u64 t; cvta.to.shared.u64 t, %1; cvt.u32.u64 %0, t; }"
        : "=r"(a) : "l"(p));
    return a;
}

#define CP_ASYNC16(dst, src)                                                  \
    asm volatile("cp.async.cg.shared.global [%0], [%1], 16;"                  \
                 :: "r"(dst), "l"(src) : "memory")
#define CP_COMMIT()                                                           \
    asm volatile("cp.async.commit_group;" ::: "memory")
#define CP_WAIT0()                                                            \
    asm volatile("cp.async.wait_group 0;" ::: "memory")
#define CP_WAIT1()                                                            \
    asm volatile("cp.async.wait_group 1;" ::: "memory")

#define LDSM_X4(r0, r1, r2, r3, addr)                                         \
    asm volatile("ldmatrix.sync.aligned.m8n8.x4.shared.b16 "                  \
                 "{%0,%1,%2,%3}, [%4];"                                       \
                 : "=r"(r0), "=r"(r1), "=r"(r2), "=r"(r3) : "r"(addr))

#define LDSM_X4_T(r0, r1, r2, r3, addr)                                       \
    asm volatile("ldmatrix.sync.aligned.m8n8.x4.trans.shared.b16 "            \
                 "{%0,%1,%2,%3}, [%4];"                                       \
                 : "=r"(r0), "=r"(r1), "=r"(r2), "=r"(r3) : "r"(addr))

#define MMA_16816_F16(d, a0, a1, a2, a3, b0, b1)                              \
    asm volatile("mma.sync.aligned.m16n8k16.row.col.f32.f16.f16.f32 "         \
                 "{%0,%1,%2,%3}, {%4,%5,%6,%7}, {%8,%9}, {%0,%1,%2,%3};"      \
                 : "+f"((d)[0]), "+f"((d)[1]), "+f"((d)[2]), "+f"((d)[3])     \
                 : "r"(a0), "r"(a1), "r"(a2), "r"(a3), "r"(b0), "r"(b1))

// Split fp32x4 -> fp16 hi + fp16 lo
__device__ __forceinline__ void split4h(float4 v, uint2& h, uint2& l) {
    __half2 h01 = __float22half2_rn(make_float2(v.x, v.y));
    __half2 h23 = __float22half2_rn(make_float2(v.z, v.w));
    float2 f01 = __half22float2(h01);
    float2 f23 = __half22float2(h23);
    __half2 l01 = __float22half2_rn(make_float2(v.x - f01.x, v.y - f01.y));
    __half2 l23 = __float22half2_rn(make_float2(v.z - f23.x, v.w - f23.y));
    h = make_uint2(*(uint32_t*)&h01, *(uint32_t*)&h23);
    l = make_uint2(*(uint32_t*)&l01, *(uint32_t*)&l23);
}

__device__ __forceinline__ void grid_barrier(int* ctr, int tid) {
    __threadfence();
    __syncthreads();
    if (tid == 0) {
        atomicAdd(ctr, 1);
        while (atomicAdd(ctr, 0) < NCTA) { }
    }
    __syncthreads();
    __threadfence();
}

// Issue all cp.async for one tile into buffer at sbuf (no syncs inside).
__device__ __forceinline__ void prefetch_tile(uint32_t sbuf, int e, int base,
                                              int nrows,
                                              const float* __restrict__ Bias,
                                              int tid) {
    // B: 128 k-rows x 16 chunks of 16B (32KB fp16 W)
    const char* WB = (const char*)(g_Wh + (size_t)e * DD * FF);
    #pragma unroll
    for (int it = 0; it < 8; it++) {
        int idx = tid + it * 256;
        int k = idx >> 4, c = idx & 15;
        CP_ASYNC16(sbuf + ABYTES + (uint32_t)(k * 272 + c * 16),
                   WB + (uint32_t)(k * 256 + c * 16));
    }
    // A: 32 rows x 32 chunks of 16B (hi|lo row = 512B); pad rows -> zero row TB
    #pragma unroll
    for (int it = 0; it < 4; it++) {
        int idx = tid + it * 256;
        int m = idx >> 5, c = idx & 31;
        int r = (m < nrows) ? g_rowOrder[base + m] : TB;
        CP_ASYNC16(sbuf + (uint32_t)(m * 528 + c * 16),
                   (const char*)g_Xs + (size_t)r * 512 + c * 16);
    }
    // bias: 512B
    if (tid < 32)
        CP_ASYNC16(sbuf + ABYTES + BBYTES + (uint32_t)(tid * 16),
                   (const char*)(Bias + e * FF) + tid * 16);
}

// ---------------------------------------------------------------------------
// Single persistent kernel: convert + sort + grouped fp16x2 HMMA GEMM.
// ---------------------------------------------------------------------------
__global__ __launch_bounds__(256, 1)
void k_all(const int* __restrict__ tidx, const float* __restrict__ X,
           const float* __restrict__ W, const float* __restrict__ Bias,
           float* __restrict__ Y) {
    extern __shared__ char smem[];
    const uint32_t sbase = smem_u32(smem);
    int tid = threadIdx.x;
    int bid = blockIdx.x;
    int wid = tid >> 5;
    int lid = tid & 31;

    // Phase A/B scratch (aliases buffer 0; used only before barrier 2)
    int* s_bins   = (int*)(smem);            // [64]
    int* s_total  = (int*)(smem + 256);      // [64]
    int* s_mybase = (int*)(smem + 512);      // [64]
    int* s_roffv  = (int*)(smem + 768);      // [64]
    int* s_toffv  = (int*)(smem + 1024);     // [65]

    // ===================== Phase A: histogram + convert ====================
    if (tid < TT) s_bins[tid] = 0;
    __syncthreads();

    int my_e = -1, my_loc = 0, my_row = -1;
    if (bid < NSORT && tid < 64) {
        my_row = bid * 64 + tid;
        my_e = tidx[my_row];
        my_e = min(max(my_e, 0), TT - 1);
        my_loc = atomicAdd(&s_bins[my_e], 1);
    }
    __syncthreads();
    if (bid < NSORT && tid < TT) g_partial[bid * TT + tid] = s_bins[tid];

    // Zero padding row of Xs
    if (bid == NCTA - 1 && tid < 128)
        ((uint32_t*)(g_Xs + (size_t)TB * 256))[tid] = 0;

    // Convert X -> fp16 hi|lo rows (512B) and W -> fp16, grid-stride
    {
        const int XF4 = TB * DD / 4;         // 262144
        const int WF4 = TT * DD * FF / 4;    // 262144
        for (int i = bid * 256 + tid; i < XF4 + WF4; i += NCTA * 256) {
            if (i < XF4) {
                int r = i >> 5, k4 = i & 31;
                uint2 h, l;
                split4h(((const float4*)X)[i], h, l);
                *(uint2*)(g_Xs + (size_t)r * 256 + k4 * 4)       = h;
                *(uint2*)(g_Xs + (size_t)r * 256 + 128 + k4 * 4) = l;
            } else {
                int j = i - XF4;
                float4 v = ((const float4*)W)[j];
                __half2 h01 = __float22half2_rn(make_float2(v.x, v.y));
                __half2 h23 = __float22half2_rn(make_float2(v.z, v.w));
                uint2 hv = make_uint2(*(uint32_t*)&h01, *(uint32_t*)&h23);
                *(uint2*)(g_Wh + (size_t)j * 4) = hv;
            }
        }
    }

    grid_barrier(&g_bar1, tid);

    // ===================== Phase B: scan + scatter + tile plan =============
    if (tid < TT) {
        int tot = 0, myb = 0;
        #pragma unroll 4
        for (int i = 0; i < NSORT; i++) {
            int p = g_partial[i * TT + tid];
            if (i < bid) myb += p;
            tot += p;
        }
        s_total[tid]  = tot;
        s_mybase[tid] = myb;
    }
    __syncthreads();

    if (tid == 0) {
        int roff = 0, toff = 0;
        #pragma unroll
        for (int e2 = 0; e2 < TT; e2++) {
            s_roffv[e2] = roff;
            s_toffv[e2] = toff;
            int nt = (s_total[e2] + TM - 1) / TM;
            roff += nt * TM;
            toff += nt;
        }
        s_toffv[TT] = toff;
    }
    __syncthreads();

    if (my_row >= 0)
        g_rowOrder[s_roffv[my_e] + s_mybase[my_e] + my_loc] = my_row;

    // Stash this CTA's tile metadata in registers (smem dies at barrier 2)
    int ntiles = s_toffv[TT];
    int te[MAXT], tbm[MAXT], trn[MAXT];
    int ntm = 0;
    #pragma unroll
    for (int j = 0; j < MAXT; j++) {
        int t = bid + j * NCTA;
        if (t < ntiles) {
            int e2 = 0;
            while (s_toffv[e2 + 1] <= t) e2++;
            int j2 = t - s_toffv[e2];
            te[j]  = e2;
            tbm[j] = s_roffv[e2] + j2 * TM;
            trn[j] = min(TM, s_total[e2] - j2 * TM);
            ntm = j + 1;
        }
    }

    grid_barrier(&g_bar2, tid);

    // ===================== Phase C: pipelined tile loop =====================
    int warpM = wid >> 2;     // 0..1  (16 rows)
    int warpN = wid & 3;      // 0..3  (32 cols)

    if (ntm > 0) prefetch_tile(sbase, te[0], tbm[0], trn[0], Bias, tid);
    CP_COMMIT();
    if (ntm > 1) prefetch_tile(sbase + BUFB, te[1], tbm[1], trn[1], Bias, tid);
    CP_COMMIT();

    for (int j = 0; j < ntm; j++) {
        if (j + 1 < ntm) { CP_WAIT1(); } else { CP_WAIT0(); }
        __syncthreads();

        uint32_t sbuf = sbase + (uint32_t)((j & 1) * BUFB);
        int e     = te[j];
        int base  = tbm[j];
        int nrows = trn[j];
        (void)e;

        float acc[4][4];
        #pragma unroll
        for (int nn = 0; nn < 4; nn++)
            #pragma unroll
            for (int q = 0; q < 4; q++) acc[nn][q] = 0.f;

        uint32_t aLane = sbuf
            + (uint32_t)((warpM * 16 + (lid & 15)) * 528 + (lid >> 4) * 16);
        uint32_t bLane = sbuf + ABYTES
            + (uint32_t)((lid & 15) * 272 + (warpN * 32 + (lid >> 4) * 8) * 2);

        #pragma unroll
        for (int k0 = 0; k0 < 256; k0 += 16) {
            int bk = k0 & 127;               // B wraps: hi and lo share W
            uint32_t a0, a1, a2, a3;
            LDSM_X4(a0, a1, a2, a3, aLane + k0 * 2);
            uint32_t bfr[2][4];
            #pragma unroll
            for (int jn = 0; jn < 2; jn++)
                LDSM_X4_T(bfr[jn][0], bfr[jn][1], bfr[jn][2], bfr[jn][3],
                          bLane + bk * 272 + jn * 32);
            #pragma unroll
            for (int jn = 0; jn < 2; jn++) {
                MMA_16816_F16(acc[jn * 2],     a0, a1, a2, a3,
                              bfr[jn][0], bfr[jn][1]);
                MMA_16816_F16(acc[jn * 2 + 1], a0, a1, a2, a3,
                              bfr[jn][2], bfr[jn][3]);
            }
        }

        // Epilogue
        const float* bias_s = (const float*)(smem + (j & 1) * BUFB
                                             + ABYTES + BBYTES);
        int m0 = warpM * 16 + (lid >> 2);
        int m1 = m0 + 8;
        int gr0 = (m0 < nrows) ? g_rowOrder[base + m0] : -1;
        int gr1 = (m1 < nrows) ? g_rowOrder[base + m1] : -1;
        int colBase = warpN * 32 + (lid & 3) * 2;
        #pragma unroll
        for (int nn = 0; nn < 4; nn++) {
            int col = colBase + nn * 8;
            float bx = bias_s[col], by = bias_s[col + 1];
            if (gr0 >= 0) {
                float2 o = make_float2(acc[nn][0] + bx, acc[nn][1] + by);
                *(float2*)&Y[(size_t)gr0 * FF + col] = o;
            }
            if (gr1 >= 0) {
                float2 o = make_float2(acc[nn][2] + bx, acc[nn][3] + by);
                *(float2*)&Y[(size_t)gr1 * FF + col] = o;
            }
        }

        __syncthreads();     // everyone done reading this buffer
        if (j + 2 < ntm) {
            prefetch_tile(sbuf, te[j + 2], tbm[j + 2], trn[j + 2], Bias, tid);
            CP_COMMIT();
        }
    }

    // Reset barrier counters for next graph replay
    if (tid == 0) {
        int d = atomicAdd(&g_dep, 1);
        if (d == NCTA - 1) {
            g_bar1 = 0; g_bar2 = 0; g_dep = 0;
            __threadfence();
        }
    }
}

// ---------------------------------------------------------------------------
extern "C" void kernel_launch(void* const* d_in, const int* in_sizes, int n_in,
                              void* d_out, int out_size) {
    const float* X    = (const float*)d_in[0];   // [B, D] fp32
    const int*   tidx = (const int*)d_in[1];     // [B] int32
    const float* W    = (const float*)d_in[2];   // [T, D, F] fp32
    const float* Bias = (const float*)d_in[3];   // [T, F] fp32
    float* Y = (float*)d_out;                    // [B, F] fp32

    (void)in_sizes; (void)n_in; (void)out_size;

    cudaFuncSetAttribute(k_all, cudaFuncAttributeMaxDynamicSharedMemorySize,
                         SMTOT);

    k_all<<<NCTA, 256, SMTOT>>>(tidx, X, W, Bias, Y);
}

// round 8
// speedup vs baseline: 1.5802x; 1.5802x over previous
#include <cuda_runtime.h>
#include <cuda_fp16.h>
#include <cstdint>

// Problem constants (fixed for MoEDense_10411000726246)
#define TB 8192     // batch
#define DD 128      // input dim (K)
#define FF 128      // output dim (N)
#define TT 64       // num experts
#define TM 32       // rows per GEMM tile
#define NBLK 32     // sort blocks (grid-barrier participants, launched first)
#define CONVBLK 264 // convert blocks

#define MAX_TILES (TB / TM + TT)        // 320
#define PAD_CAP   (TB + TT * TM)        // 10240

// Scratch (no allocations allowed)
__device__ int g_partial[NBLK * TT];
__device__ int g_arrive = 0;
__device__ int g_depart = 0;
__device__ int g_tileExpert[MAX_TILES];
__device__ int g_tileBase[MAX_TILES];
__device__ int g_tileRows[MAX_TILES];
__device__ int g_rowOrder[PAD_CAP];

// Pre-converted fp16 operands (X gets one extra all-zero row at TB)
__device__ __half g_Xh[(TB + 1) * DD];
__device__ __half g_Wh[TT * DD * FF];

// ---------------------------------------------------------------------------
__device__ __forceinline__ uint32_t smem_u32(const void* p) {
    uint32_t a;
    asm("{ .reg .u64 t; cvta.to.shared.u64 t, %1; cvt.u32.u64 %0, t; }"
        : "=r"(a) : "l"(p));
    return a;
}

#define CP_ASYNC16(dst, src)                                                  \
    asm volatile("cp.async.cg.shared.global [%0], [%1], 16;"                  \
                 :: "r"(dst), "l"(src) : "memory")
#define CP_COMMIT_WAIT()                                                      \
    asm volatile("cp.async.commit_group;\n\tcp.async.wait_group 0;"           \
                 ::: "memory")

#define LDSM_X4(r0, r1, r2, r3, addr)                                         \
    asm volatile("ldmatrix.sync.aligned.m8n8.x4.shared.b16 "                  \
                 "{%0,%1,%2,%3}, [%4];"                                       \
                 : "=r"(r0), "=r"(r1), "=r"(r2), "=r"(r3) : "r"(addr))

#define LDSM_X4_T(r0, r1, r2, r3, addr)                                       \
    asm volatile("ldmatrix.sync.aligned.m8n8.x4.trans.shared.b16 "            \
                 "{%0,%1,%2,%3}, [%4];"                                       \
                 : "=r"(r0), "=r"(r1), "=r"(r2), "=r"(r3) : "r"(addr))

#define MMA_16816_F16(d, a0, a1, a2, a3, b0, b1)                              \
    asm volatile("mma.sync.aligned.m16n8k16.row.col.f32.f16.f16.f32 "         \
                 "{%0,%1,%2,%3}, {%4,%5,%6,%7}, {%8,%9}, {%0,%1,%2,%3};"      \
                 : "+f"((d)[0]), "+f"((d)[1]), "+f"((d)[2]), "+f"((d)[3])     \
                 : "r"(a0), "r"(a1), "r"(a2), "r"(a3), "r"(b0), "r"(b1))

// ---------------------------------------------------------------------------
// K_prep: blocks [0,32) = fused histogram/scan/plan/scatter (grid barrier
// among themselves); blocks [32,296) = fp32 -> fp16 convert of X and W.
// ---------------------------------------------------------------------------
__global__ __launch_bounds__(256) void k_prep(const int* __restrict__ tidx,
                                              const float* __restrict__ X,
                                              const float* __restrict__ W) {
    int t = threadIdx.x;
    int b = blockIdx.x;

    if (b >= NBLK) {
        // ---- convert path ----
        int cb = b - NBLK;
        if (cb == 0 && t < 64) {   // zero the padding row TB (256B)
            ((uint32_t*)(g_Xh + (size_t)TB * DD))[t] = 0;
        }
        const int XF4 = TB * DD / 4;        // 262144
        const int WF4 = TT * DD * FF / 4;   // 262144
        for (int i = cb * 256 + t; i < XF4 + WF4; i += CONVBLK * 256) {
            float4 v;
            __half* dst;
            if (i < XF4) { v = ((const float4*)X)[i]; dst = g_Xh + (size_t)i * 4; }
            else { int j = i - XF4; v = ((const float4*)W)[j]; dst = g_Wh + (size_t)j * 4; }
            __half2 h01 = __float22half2_rn(make_float2(v.x, v.y));
            __half2 h23 = __float22half2_rn(make_float2(v.z, v.w));
            uint2 hv = make_uint2(*(uint32_t*)&h01, *(uint32_t*)&h23);
            *(uint2*)dst = hv;
        }
        return;
    }

    // ---- sort path (blocks 0..31) ----
    __shared__ int s_bins[TT];
    __shared__ int s_total[TT];
    __shared__ int s_base[TT];
    __shared__ int s_roff[TT];
    __shared__ int s_toff[TT];
    __shared__ int s_ntiles;

    if (t < TT) s_bins[t] = 0;
    __syncthreads();

    int row = b * 256 + t;
    int e = tidx[row];
    e = min(max(e, 0), TT - 1);
    int loc = atomicAdd(&s_bins[e], 1);
    __syncthreads();

    if (t < TT) g_partial[b * TT + t] = s_bins[t];
    __threadfence();
    __syncthreads();

    if (t == 0) {
        atomicAdd(&g_arrive, 1);
        while (atomicAdd(&g_arrive, 0) < NBLK) { }
    }
    __syncthreads();
    __threadfence();

    if (t < TT) {
        int tot = 0, mybase = 0;
        #pragma unroll 4
        for (int i = 0; i < NBLK; i++) {
            int p = g_partial[i * TT + t];
            if (i < b) mybase += p;
            tot += p;
        }
        s_total[t] = tot;
        s_base[t] = mybase;
    }
    __syncthreads();

    if (t == 0) {
        int roff = 0, toff = 0;
        #pragma unroll
        for (int i = 0; i < TT; i++) {
            s_roff[i] = roff;
            s_toff[i] = toff;
            int nt = (s_total[i] + TM - 1) / TM;
            roff += nt * TM;
            toff += nt;
        }
        s_ntiles = toff;
    }
    __syncthreads();

    if (t < TT) s_base[t] += s_roff[t];
    __syncthreads();

    g_rowOrder[s_base[e] + loc] = row;

    if (b == 0) {
        if (t < TT) {
            int tot = s_total[t];
            int nt = (tot + TM - 1) / TM;
            int tb = s_toff[t];
            int rb = s_roff[t];
            for (int j = 0; j < nt; j++) {
                g_tileExpert[tb + j] = t;
                g_tileBase[tb + j]   = rb + j * TM;
                g_tileRows[tb + j]   = min(TM, tot - j * TM);
            }
        }
        __syncthreads();
        for (int idx = s_ntiles + t; idx < MAX_TILES; idx += 256)
            g_tileExpert[idx] = -1;
    }

    if (t == 0) {
        int d = atomicAdd(&g_depart, 1);
        if (d == NBLK - 1) { g_arrive = 0; g_depart = 0; __threadfence(); }
    }
}

// ---------------------------------------------------------------------------
// K_gemm: 32x128 tile per CTA, single fp16 pass K=128.
//   256 threads = 8 warps (2M x 4N); warp tile 16x32. fp32 accumulation.
// ---------------------------------------------------------------------------
#define APAD 136
#define AROWB (APAD * 2)                 // 272 bytes (128 fp16 + 16B pad)
#define SM_A   0
#define SM_B   (SM_A + TM * AROWB)       // 8704
#define SM_BIAS (SM_B + DD * AROWB)      // 43520
#define SM_ROWS (SM_BIAS + FF * 4)       // 44032
#define SM_TOTAL (SM_ROWS + TM * 4)      // 44160

__global__ __launch_bounds__(256, 2)
void k_gemm(const float* __restrict__ Bias, float* __restrict__ Y) {
    extern __shared__ char smem[];
    const uint32_t sbase = smem_u32(smem);

    int tile = blockIdx.x;
    int e = g_tileExpert[tile];
    if (e < 0) return;
    int base  = g_tileBase[tile];
    int nrows = g_tileRows[tile];
    int tid = threadIdx.x;
    int wid = tid >> 5;
    int lid = tid & 31;

    int* rows_s   = (int*)(smem + SM_ROWS);
    float* bias_s = (float*)(smem + SM_BIAS);

    if (tid < TM) rows_s[tid] = (tid < nrows) ? g_rowOrder[base + tid] : -1;
    if (tid >= 128) bias_s[tid - 128] = Bias[e * FF + (tid - 128)];

    // --- B: cp.async 128 k-rows x 16 chunks of 16B (fp16 W, 32KB)
    {
        const char* WB = (const char*)(g_Wh + (size_t)e * DD * FF);
        #pragma unroll
        for (int it = 0; it < 8; it++) {
            int idx = tid + it * 256;          // 2048
            int k     = idx >> 4;
            int chunk = idx & 15;
            CP_ASYNC16(sbase + SM_B + (uint32_t)(k * AROWB + chunk * 16),
                       WB + (uint32_t)(k * 256 + chunk * 16));
        }
    }
    __syncthreads();   // rows_s ready

    // --- A: cp.async 32 rows x 16 chunks of 16B (fp16 row = 256B)
    {
        #pragma unroll
        for (int it = 0; it < 2; it++) {
            int idx = tid + it * 256;          // 512
            int m     = idx >> 4;
            int chunk = idx & 15;
            int r = rows_s[m];
            int r2 = (r < 0) ? TB : r;
            CP_ASYNC16(sbase + SM_A + (uint32_t)(m * AROWB + chunk * 16),
                       (const char*)g_Xh + (size_t)r2 * 256 + chunk * 16);
        }
    }
    CP_COMMIT_WAIT();
    __syncthreads();

    // --- Warp tiling: 8 warps = 2(M) x 4(N); warp tile 16x32
    int warpM = wid >> 2;     // 0..1
    int warpN = wid & 3;      // 0..3

    float acc[4][4];
    #pragma unroll
    for (int nn = 0; nn < 4; nn++)
        #pragma unroll
        for (int q = 0; q < 4; q++) acc[nn][q] = 0.f;

    uint32_t aLane = sbase + SM_A
                   + (uint32_t)((warpM * 16 + (lid & 15)) * AROWB
                   + (lid >> 4) * 16);
    uint32_t bLane = sbase + SM_B
                   + (uint32_t)((lid & 15) * AROWB
                   + (warpN * 32 + (lid >> 4) * 8) * 2);

    #pragma unroll
    for (int k0 = 0; k0 < DD; k0 += 16) {
        uint32_t a0, a1, a2, a3;
        LDSM_X4(a0, a1, a2, a3, aLane + k0 * 2);
        uint32_t bfr[2][4];
        #pragma unroll
        for (int jn = 0; jn < 2; jn++)
            LDSM_X4_T(bfr[jn][0], bfr[jn][1], bfr[jn][2], bfr[jn][3],
                      bLane + k0 * AROWB + jn * 32);
        #pragma unroll
        for (int jn = 0; jn < 2; jn++) {
            MMA_16816_F16(acc[jn * 2],     a0, a1, a2, a3,
                          bfr[jn][0], bfr[jn][1]);
            MMA_16816_F16(acc[jn * 2 + 1], a0, a1, a2, a3,
                          bfr[jn][2], bfr[jn][3]);
        }
    }

    // --- Epilogue: c-frag layout -> gmem with bias
    int m0 = warpM * 16 + (lid >> 2);
    int m1 = m0 + 8;
    int gr0 = rows_s[m0];
    int gr1 = rows_s[m1];
    int colBase = warpN * 32 + (lid & 3) * 2;
    #pragma unroll
    for (int nn = 0; nn < 4; nn++) {
        int col = colBase + nn * 8;
        float bx = bias_s[col], by = bias_s[col + 1];
        if (gr0 >= 0) {
            float2 o = make_float2(acc[nn][0] + bx, acc[nn][1] + by);
            *(float2*)&Y[(size_t)gr0 * FF + col] = o;
        }
        if (gr1 >= 0) {
            float2 o = make_float2(acc[nn][2] + bx, acc[nn][3] + by);
            *(float2*)&Y[(size_t)gr1 * FF + col] = o;
        }
    }
}

// ---------------------------------------------------------------------------
extern "C" void kernel_launch(void* const* d_in, const int* in_sizes, int n_in,
                              void* d_out, int out_size) {
    const float* X    = (const float*)d_in[0];   // [B, D] fp32
    const int*   tidx = (const int*)d_in[1];     // [B] int32
    const float* W    = (const float*)d_in[2];   // [T, D, F] fp32
    const float* Bias = (const float*)d_in[3];   // [T, F] fp32
    float* Y = (float*)d_out;                    // [B, F] fp32

    (void)in_sizes; (void)n_in; (void)out_size;

    cudaFuncSetAttribute(k_gemm, cudaFuncAttributeMaxDynamicSharedMemorySize,
                         SM_TOTAL);

    k_prep<<<NBLK + CONVBLK, 256>>>(tidx, X, W);
    k_gemm<<<MAX_TILES, 256, SM_TOTAL>>>(Bias, Y);
}